// round 6
// baseline (speedup 1.0000x reference)
#include <cuda_runtime.h>
#include <cstdint>

// Problem constants
#define BB   32
#define SS   64
#define DD   512
#define MM   8192
#define NHD  8
#define HD   64
#define NTOK (BB * SS)          // 2048

// Scratch (device globals per allocation rules)
__device__ float g_Q[NTOK * DD];          // 2048 x 512
__device__ float g_KV[MM * 2 * DD];       // 8192 x 1024   (K cols 0..511, V cols 512..1023)
__device__ float g_AO[NTOK * DD];         // 2048 x 512

// ---------------------------------------------------------------------------
// Generic fp32 GEMM: C[MxN] = A[MxK] * B[NxK]^T + bias[N]
// 64x64 block tile, BK=16, 256 threads, 4x4 register micro-tile.
// smem tiles stored k-major (transposed) so inner loop uses float4 LDS.
// Requires Mrows%64==0, N%64==0, K%16==0 (true for all three calls).
// ---------------------------------------------------------------------------
__global__ __launch_bounds__(256) void gemm_abt(
    const float* __restrict__ A, const float* __restrict__ Bm,
    const float* __restrict__ bias, float* __restrict__ C,
    int K, int N)
{
    __shared__ float As[16 * 64];
    __shared__ float Bs[16 * 64];

    const int tid = threadIdx.x;
    const int tx = tid & 15;       // n micro index
    const int ty = tid >> 4;       // m micro index
    const int bm = blockIdx.y * 64;
    const int bn = blockIdx.x * 64;

    const int lr = tid >> 2;            // 0..63 row within tile for loads
    const int lk = (tid & 3) * 4;       // 0,4,8,12 k offset for loads
    const float* Ab = A  + (size_t)(bm + lr) * K + lk;
    const float* Bb = Bm + (size_t)(bn + lr) * K + lk;

    float acc[4][4];
    #pragma unroll
    for (int i = 0; i < 4; i++)
        #pragma unroll
        for (int j = 0; j < 4; j++) acc[i][j] = 0.f;

    for (int k0 = 0; k0 < K; k0 += 16) {
        float4 a4 = *(const float4*)(Ab + k0);
        float4 b4 = *(const float4*)(Bb + k0);
        As[(lk + 0) * 64 + lr] = a4.x;
        As[(lk + 1) * 64 + lr] = a4.y;
        As[(lk + 2) * 64 + lr] = a4.z;
        As[(lk + 3) * 64 + lr] = a4.w;
        Bs[(lk + 0) * 64 + lr] = b4.x;
        Bs[(lk + 1) * 64 + lr] = b4.y;
        Bs[(lk + 2) * 64 + lr] = b4.z;
        Bs[(lk + 3) * 64 + lr] = b4.w;
        __syncthreads();

        #pragma unroll
        for (int k = 0; k < 16; k++) {
            float4 av = *(const float4*)&As[k * 64 + ty * 4];
            float4 bv = *(const float4*)&Bs[k * 64 + tx * 4];
            float a[4] = {av.x, av.y, av.z, av.w};
            float b[4] = {bv.x, bv.y, bv.z, bv.w};
            #pragma unroll
            for (int i = 0; i < 4; i++)
                #pragma unroll
                for (int j = 0; j < 4; j++)
                    acc[i][j] += a[i] * b[j];
        }
        __syncthreads();
    }

    #pragma unroll
    for (int i = 0; i < 4; i++) {
        int row = bm + ty * 4 + i;
        int col = bn + tx * 4;
        float4 o;
        o.x = acc[i][0] + bias[col + 0];
        o.y = acc[i][1] + bias[col + 1];
        o.z = acc[i][2] + bias[col + 2];
        o.w = acc[i][3] + bias[col + 3];
        *(float4*)&C[(size_t)row * N + col] = o;
    }
}

// ---------------------------------------------------------------------------
// Flash-attention kernel. One block per (b, h). 256 threads.
// Streams M in 64-wide tiles with online softmax. S kept TRANSPOSED in smem
// (St[m][s]) so both inner GEMMs read float4-vectorized, and the softmax
// column reduction is bank-conflict-free.
// Dynamic smem layout (floats):
//   Qt  [64][64]  (k-major, prescaled by 1/8)   @ 0
//   Kt  [64][64]  (k-major)                     @ 4096
//   Vs  [64][64]  (row-major)                   @ 8192
//   St  [64][68]  (pad 68)                      @ 12288
//   mrow[64] lrow[64] crow[64]                  @ 16640/16704/16768
//   red [256]                                   @ 16832
// total 17088 floats = 68352 bytes
// ---------------------------------------------------------------------------
#define ATTN_SMEM_BYTES (17088 * 4)

__global__ __launch_bounds__(256) void attn_kernel()
{
    extern __shared__ float sm[];
    float* Qt   = sm;
    float* Kt   = sm + 4096;
    float* Vs   = sm + 8192;
    float* St   = sm + 12288;
    float* mrow = sm + 16640;
    float* lrow = sm + 16704;
    float* crow = sm + 16768;
    float* red  = sm + 16832;

    const int tid = threadIdx.x;
    const int h = blockIdx.x;
    const int b = blockIdx.y;
    const int tx = tid & 15;
    const int ty = tid >> 4;
    const int sq = tid & 63;      // softmax: column (query) index
    const int part = tid >> 6;    // softmax: 4 partial reducers per column

    // Load Q tile, transposed & prescaled
    #pragma unroll
    for (int p = 0; p < 4; p++) {
        int idx = p * 256 + tid;
        int s = idx >> 4;
        int d4 = (idx & 15) * 4;
        float4 q = *(const float4*)&g_Q[(size_t)(b * 64 + s) * DD + h * HD + d4];
        Qt[(d4 + 0) * 64 + s] = q.x * 0.125f;
        Qt[(d4 + 1) * 64 + s] = q.y * 0.125f;
        Qt[(d4 + 2) * 64 + s] = q.z * 0.125f;
        Qt[(d4 + 3) * 64 + s] = q.w * 0.125f;
    }
    if (tid < 64) { mrow[tid] = -1e30f; lrow[tid] = 0.f; }

    float accO[4][4];
    #pragma unroll
    for (int i = 0; i < 4; i++)
        #pragma unroll
        for (int j = 0; j < 4; j++) accO[i][j] = 0.f;

    for (int t = 0; t < MM / 64; t++) {
        __syncthreads();  // protect Qt (first iter) / St,Vs (later iters) before overwrite

        // Load K tile (transposed) and V tile (row-major)
        #pragma unroll
        for (int p = 0; p < 4; p++) {
            int idx = p * 256 + tid;
            int m = idx >> 4;
            int d4 = (idx & 15) * 4;
            const float* base = &g_KV[(size_t)(t * 64 + m) * (2 * DD) + h * HD + d4];
            float4 kv = *(const float4*)base;
            Kt[(d4 + 0) * 64 + m] = kv.x;
            Kt[(d4 + 1) * 64 + m] = kv.y;
            Kt[(d4 + 2) * 64 + m] = kv.z;
            Kt[(d4 + 3) * 64 + m] = kv.w;
            float4 vv = *(const float4*)(base + DD);
            *(float4*)&Vs[m * 64 + d4] = vv;
        }
        __syncthreads();

        // S GEMM: St[m][s] = sum_d Kt[d][m] * Qt[d][s]
        float accS[4][4];
        #pragma unroll
        for (int i = 0; i < 4; i++)
            #pragma unroll
            for (int j = 0; j < 4; j++) accS[i][j] = 0.f;
        #pragma unroll 8
        for (int d = 0; d < 64; d++) {
            float4 av = *(const float4*)&Kt[d * 64 + ty * 4];
            float4 bv = *(const float4*)&Qt[d * 64 + tx * 4];
            float a[4] = {av.x, av.y, av.z, av.w};
            float bq[4] = {bv.x, bv.y, bv.z, bv.w};
            #pragma unroll
            for (int i = 0; i < 4; i++)
                #pragma unroll
                for (int j = 0; j < 4; j++)
                    accS[i][j] += a[i] * bq[j];
        }
        #pragma unroll
        for (int i = 0; i < 4; i++) {
            float4 o = make_float4(accS[i][0], accS[i][1], accS[i][2], accS[i][3]);
            *(float4*)&St[(ty * 4 + i) * 68 + tx * 4] = o;
        }
        __syncthreads();

        // Online softmax over columns of St (per query s)
        float lm = -1e30f;
        #pragma unroll
        for (int i = 0; i < 16; i++)
            lm = fmaxf(lm, St[(part * 16 + i) * 68 + sq]);
        red[part * 64 + sq] = lm;
        __syncthreads();

        float m_old = mrow[sq];
        float m_new = fmaxf(fmaxf(fmaxf(red[sq], red[64 + sq]),
                                  fmaxf(red[128 + sq], red[192 + sq])), m_old);
        float c = __expf(m_old - m_new);

        float ls = 0.f;
        #pragma unroll
        for (int i = 0; i < 16; i++) {
            float* p = &St[(part * 16 + i) * 68 + sq];
            float e = __expf(*p - m_new);
            *p = e;
            ls += e;
        }
        __syncthreads();                 // all reads of red done before reuse
        red[part * 64 + sq] = ls;
        __syncthreads();
        if (part == 0) {
            lrow[sq] = lrow[sq] * c + (red[sq] + red[64 + sq] + red[128 + sq] + red[192 + sq]);
            mrow[sq] = m_new;
            crow[sq] = c;
        }
        __syncthreads();

        // Rescale accumulator rows by correction factor
        #pragma unroll
        for (int i = 0; i < 4; i++) {
            float f = crow[ty * 4 + i];
            #pragma unroll
            for (int j = 0; j < 4; j++) accO[i][j] *= f;
        }

        // O GEMM: accO[s][d] += sum_m St[m][s] * Vs[m][d]
        #pragma unroll 8
        for (int m = 0; m < 64; m++) {
            float4 av = *(const float4*)&St[m * 68 + ty * 4];
            float4 bv = *(const float4*)&Vs[m * 64 + tx * 4];
            float a[4] = {av.x, av.y, av.z, av.w};
            float vb[4] = {bv.x, bv.y, bv.z, bv.w};
            #pragma unroll
            for (int i = 0; i < 4; i++)
                #pragma unroll
                for (int j = 0; j < 4; j++)
                    accO[i][j] += a[i] * vb[j];
        }
    }

    __syncthreads();
    #pragma unroll
    for (int i = 0; i < 4; i++) {
        int s = ty * 4 + i;
        float inv = 1.f / lrow[s];
        float4 o = make_float4(accO[i][0] * inv, accO[i][1] * inv,
                               accO[i][2] * inv, accO[i][3] * inv);
        *(float4*)&g_AO[(size_t)(b * 64 + s) * DD + h * HD + tx * 4] = o;
    }
}

// ---------------------------------------------------------------------------
// Bank update: new_bank[r] = memory[(r - ptr) mod M] if that index < N else bank[r]
// One block per bank row, 128 threads x float4 = 512 floats.
// ---------------------------------------------------------------------------
__global__ __launch_bounds__(128) void bank_update(
    const float* __restrict__ memory, const float* __restrict__ bank,
    const int* __restrict__ ptrp, float* __restrict__ outbank)
{
    int r = blockIdx.x;
    int ptr = ptrp[0];                        // low 32 bits are correct for i32/i64
    int rel = (r - ptr) % MM;
    if (rel < 0) rel += MM;
    const float* src = (rel < NTOK) ? (memory + (size_t)rel * DD)
                                    : (bank + (size_t)r * DD);
    float4 v = *(const float4*)(src + threadIdx.x * 4);
    *(float4*)(outbank + (size_t)r * DD + threadIdx.x * 4) = v;
}

// ---------------------------------------------------------------------------
// Launch. Inputs (metadata order): query, memory, memory_bank, in_proj_w,
// in_proj_b, out_proj_w, out_proj_b, ptr.
// Output: [retrieved (2048x512) | new_bank (8192x512)] fp32.
// ---------------------------------------------------------------------------
extern "C" void kernel_launch(void* const* d_in, const int* in_sizes, int n_in,
                              void* d_out, int out_size)
{
    const float* query  = (const float*)d_in[0];
    const float* memory = (const float*)d_in[1];
    const float* bank   = (const float*)d_in[2];
    const float* ipw    = (const float*)d_in[3];
    const float* ipb    = (const float*)d_in[4];
    const float* opw    = (const float*)d_in[5];
    const float* opb    = (const float*)d_in[6];
    const int*   ptr    = (const int*)d_in[7];
    float* out = (float*)d_out;

    float *pQ, *pKV, *pAO;
    cudaGetSymbolAddress((void**)&pQ, g_Q);
    cudaGetSymbolAddress((void**)&pKV, g_KV);
    cudaGetSymbolAddress((void**)&pAO, g_AO);

    // 1) Q = query @ Wq^T + bq           [2048 x 512]
    gemm_abt<<<dim3(DD / 64, NTOK / 64), 256>>>(query, ipw, ipb, pQ, DD, DD);

    // 2) K|V = bank @ [Wk;Wv]^T + [bk;bv]  [8192 x 1024]
    gemm_abt<<<dim3(2 * DD / 64, MM / 64), 256>>>(bank, ipw + (size_t)DD * DD,
                                                  ipb + DD, pKV, DD, 2 * DD);

    // 3) Attention (flash, online softmax), writes g_AO [2048 x 512]
    cudaFuncSetAttribute(attn_kernel, cudaFuncAttributeMaxDynamicSharedMemorySize,
                         ATTN_SMEM_BYTES);
    attn_kernel<<<dim3(NHD, BB), 256, ATTN_SMEM_BYTES>>>();

    // 4) retrieved = AO @ out_proj_w^T + b  -> out[0 : 2048*512]
    gemm_abt<<<dim3(DD / 64, NTOK / 64), 256>>>(pAO, opw, opb, out, DD, DD);

    // 5) new_bank -> out[2048*512 : ]
    bank_update<<<MM, 128>>>(memory, bank, ptr, out + (size_t)NTOK * DD);
}